// round 12
// baseline (speedup 1.0000x reference)
#include <cuda_runtime.h>
#include <cuda_bf16.h>
#include <math.h>
#include <stdint.h>

#define N_TOK 8192
#define D_IN  1024
#define D_HEAD 128

typedef uint32_t u32;

// ---------------------------------------------------------------------------
// Device-global scratch.
// ---------------------------------------------------------------------------
__device__ __align__(16) __nv_bfloat16 g_Xh[(size_t)N_TOK * D_IN];
__device__ __align__(16) __nv_bfloat16 g_Xl[(size_t)N_TOK * D_IN];
__device__ __align__(16) __nv_bfloat16 g_Wh[3 * D_HEAD * D_IN];
__device__ __align__(16) __nv_bfloat16 g_Wl[3 * D_HEAD * D_IN];
__device__ __align__(16) __nv_bfloat16 g_Qh[N_TOK * D_HEAD];
__device__ __align__(16) __nv_bfloat16 g_Ql[N_TOK * D_HEAD];
__device__ __align__(16) __nv_bfloat16 g_Kh[N_TOK * D_HEAD];
__device__ __align__(16) __nv_bfloat16 g_Kl[N_TOK * D_HEAD];
__device__ __align__(16) __nv_bfloat16 g_Vth[N_TOK * D_HEAD];
__device__ __align__(16) __nv_bfloat16 g_Vtl[N_TOK * D_HEAD];
// split-K partials (unnormalized O, per key-half) + log2-domain m,l
__device__ float g_Op[2][(size_t)N_TOK * D_HEAD];
__device__ float g_m[2][N_TOK];
__device__ float g_l[2][N_TOK];

__device__ __forceinline__ void split_bf16(float v, __nv_bfloat16& h, __nv_bfloat16& l) {
  h = __float2bfloat16(v);
  l = __float2bfloat16(v - __bfloat162float(h));
}

__device__ __forceinline__ u32 smem_u32(const void* p) {
  u32 a;
  asm("{ .reg .u64 t; cvta.to.shared.u64 t, %1; cvt.u32.u64 %0, t; }" : "=r"(a) : "l"(p));
  return a;
}
__device__ __forceinline__ void cp16(u32 dst, const void* src) {
  asm volatile("cp.async.cg.shared.global [%0], [%1], 16;" :: "r"(dst), "l"(src));
}
#define CP_COMMIT() asm volatile("cp.async.commit_group;" ::: "memory")
#define CP_WAIT0()  asm volatile("cp.async.wait_group 0;" ::: "memory")
#define CP_WAIT1()  asm volatile("cp.async.wait_group 1;" ::: "memory")

// m16n8k16 row.col bf16 -> f32 (HMMA; portable PTX)
__device__ __forceinline__ void mma16816(float* d, u32 a0, u32 a1, u32 a2, u32 a3,
                                         u32 b0, u32 b1) {
  asm volatile(
      "mma.sync.aligned.m16n8k16.row.col.f32.bf16.bf16.f32 "
      "{%0,%1,%2,%3}, {%4,%5,%6,%7}, {%8,%9}, {%0,%1,%2,%3};"
      : "+f"(d[0]), "+f"(d[1]), "+f"(d[2]), "+f"(d[3])
      : "r"(a0), "r"(a1), "r"(a2), "r"(a3), "r"(b0), "r"(b1));
}
__device__ __forceinline__ u32 cvt2(float hi, float lo) {
  u32 d;
  asm("cvt.rn.bf16x2.f32 %0, %1, %2;" : "=r"(d) : "f"(hi), "f"(lo));
  return d;
}
// fast 2^x (softmax runs in log2 domain; 1/ln2 folded into Q scale)
__device__ __forceinline__ float ex2(float x) {
  float y;
  asm("ex2.approx.f32 %0, %1;" : "=f"(y) : "f"(x));
  return y;
}

// ---------------------------------------------------------------------------
// Split kernels: fp32 -> bf16 hi/lo.
// ---------------------------------------------------------------------------
__device__ __forceinline__ void split8_store(const float* v, __nv_bfloat16* dh,
                                             __nv_bfloat16* dl) {
  u32 hw[4], lw[4];
#pragma unroll
  for (int j = 0; j < 4; j++) {
    __nv_bfloat16 h0, l0, h1, l1;
    split_bf16(v[2 * j], h0, l0);
    split_bf16(v[2 * j + 1], h1, l1);
    hw[j] = ((u32)__bfloat16_as_ushort(h1) << 16) | __bfloat16_as_ushort(h0);
    lw[j] = ((u32)__bfloat16_as_ushort(l1) << 16) | __bfloat16_as_ushort(l0);
  }
  *(uint4*)dh = make_uint4(hw[0], hw[1], hw[2], hw[3]);
  *(uint4*)dl = make_uint4(lw[0], lw[1], lw[2], lw[3]);
}

__global__ __launch_bounds__(256) void split_x_kernel(const float* __restrict__ X) {
  size_t i = ((size_t)blockIdx.x * 256 + threadIdx.x) * 8;
  float4 f0 = *(const float4*)&X[i];
  float4 f1 = *(const float4*)&X[i + 4];
  float v[8] = {f0.x, f0.y, f0.z, f0.w, f1.x, f1.y, f1.z, f1.w};
  split8_store(v, &g_Xh[i], &g_Xl[i]);
}

__global__ __launch_bounds__(256) void split_w_kernel(
    const float* __restrict__ Wq, const float* __restrict__ Wk,
    const float* __restrict__ Wv) {
  const int y = blockIdx.y;
  const float* W = (y == 0) ? Wq : (y == 1 ? Wk : Wv);
  size_t i = ((size_t)blockIdx.x * 256 + threadIdx.x) * 8;
  float4 f0 = *(const float4*)&W[i];
  float4 f1 = *(const float4*)&W[i + 4];
  float v[8] = {f0.x, f0.y, f0.z, f0.w, f1.x, f1.y, f1.z, f1.w};
  size_t o = (size_t)y * D_HEAD * D_IN + i;
  split8_store(v, &g_Wh[o], &g_Wl[o]);
}

// ---------------------------------------------------------------------------
// HMMA projection, double-buffered k-loop (unchanged from R11).
// ---------------------------------------------------------------------------
#define PSTR 80
#define PXH 0
#define PXL 10240
#define PWH 20480
#define PWL 30720
#define PSTAGE 40960
#define PROJ_SMEM (2 * PSTAGE)

__global__ __launch_bounds__(256, 2) void proj_mma_kernel() {
  extern __shared__ __align__(16) char psm[];
  const u32 pb = smem_u32(psm);

  const int y = blockIdx.y;
  const int bm = blockIdx.x;
  const int tid = threadIdx.x;
  const int w = tid >> 5;
  const int lane = tid & 31;
  const int g = lane >> 2;
  const int t = lane & 3;

  const char* xh = (const char*)g_Xh;
  const char* xl = (const char*)g_Xl;
  const char* wh = (const char*)(g_Wh + (size_t)y * D_HEAD * D_IN);
  const char* wl = (const char*)(g_Wl + (size_t)y * D_HEAD * D_IN);

  auto issue_chunk = [&](int kc32, int st) {
    const u32 base = pb + st * PSTAGE;
    const int k0 = kc32 * 32;
#pragma unroll
    for (int p = 0; p < 2; p++) {
      int idx = tid + 256 * p;
      int row = idx >> 2, sub = idx & 3;
      int so = row * PSTR + sub * 16;
      size_t xoff = ((size_t)(bm * 128 + row) * D_IN + k0) * 2 + sub * 16;
      size_t woff = ((size_t)row * D_IN + k0) * 2 + sub * 16;
      cp16(base + PXH + so, xh + xoff);
      cp16(base + PXL + so, xl + xoff);
      cp16(base + PWH + so, wh + woff);
      cp16(base + PWL + so, wl + woff);
    }
  };

  float o[16][4];
#pragma unroll
  for (int i = 0; i < 16; i++)
#pragma unroll
    for (int j = 0; j < 4; j++) o[i][j] = 0.0f;

  issue_chunk(0, 0);
  CP_COMMIT();

#pragma unroll 1
  for (int kc32 = 0; kc32 < 32; kc32++) {
    if (kc32 < 31) {
      issue_chunk(kc32 + 1, (kc32 + 1) & 1);
      CP_COMMIT();
      CP_WAIT1();
    } else {
      CP_WAIT0();
    }
    __syncthreads();

    const char* sm = psm + (kc32 & 1) * PSTAGE;
    const int oX = (16 * w + g) * PSTR + t * 4;
#pragma unroll
    for (int kc = 0; kc < 2; kc++) {
      const int qo = oX + kc * 32;
      u32 ah0 = *(const u32*)(sm + PXH + qo);
      u32 ah1 = *(const u32*)(sm + PXH + qo + 8 * PSTR);
      u32 ah2 = *(const u32*)(sm + PXH + qo + 16);
      u32 ah3 = *(const u32*)(sm + PXH + qo + 8 * PSTR + 16);
      u32 al0 = *(const u32*)(sm + PXL + qo);
      u32 al1 = *(const u32*)(sm + PXL + qo + 8 * PSTR);
      u32 al2 = *(const u32*)(sm + PXL + qo + 16);
      u32 al3 = *(const u32*)(sm + PXL + qo + 8 * PSTR + 16);
#pragma unroll
      for (int nf = 0; nf < 16; nf++) {
        const int bo = (8 * nf + g) * PSTR + t * 4 + kc * 32;
        u32 bh0 = *(const u32*)(sm + PWH + bo);
        u32 bh1 = *(const u32*)(sm + PWH + bo + 16);
        float* d = o[nf];
        mma16816(d, ah0, ah1, ah2, ah3, bh0, bh1);
        mma16816(d, al0, al1, al2, al3, bh0, bh1);
        u32 bl0 = *(const u32*)(sm + PWL + bo);
        u32 bl1 = *(const u32*)(sm + PWL + bo + 16);
        mma16816(d, ah0, ah1, ah2, ah3, bl0, bl1);
      }
    }
    __syncthreads();
  }

  // Q scaled by sqrt(128)/ln(2): softmax runs in log2 domain.
  const float scale = 16.32223134f;
#pragma unroll
  for (int nf = 0; nf < 16; nf++) {
    int c0 = 8 * nf + 2 * t;
    int R0 = bm * 128 + 16 * w + g;
#pragma unroll
    for (int q = 0; q < 4; q++) {
      int R = R0 + (q >> 1) * 8;
      int c = c0 + (q & 1);
      float v = o[nf][q];
      __nv_bfloat16 h, l;
      if (y == 0) {
        split_bf16(v * scale, h, l);
        g_Qh[(size_t)R * D_HEAD + c] = h;
        g_Ql[(size_t)R * D_HEAD + c] = l;
      } else if (y == 1) {
        split_bf16(v, h, l);
        g_Kh[(size_t)R * D_HEAD + c] = h;
        g_Kl[(size_t)R * D_HEAD + c] = l;
      } else {
        split_bf16(v, h, l);
        size_t idx = (size_t)(R >> 7) * 16384 + (size_t)c * 128 + (R & 127);
        g_Vth[idx] = h;
        g_Vtl[idx] = l;
      }
    }
  }
}

// ---------------------------------------------------------------------------
// Flash kernel v4: R11 geometry (BM=128, BN=64, rg4 x kh2, CTA split-K) with
// register-neutral cross-tile S prefetch: after softmax+P-pack, the s regs are
// dead -> reuse them as accumulators for S(t+1), then run PV(t).
// ---------------------------------------------------------------------------
#define RSTR 272
#define VSTR 144
#define SQH 0
#define QLO 34816
#define SBUF 69632
#define BKH 0
#define BKL 17408
#define BVH 34816
#define BVL 53248
#define BUFSZ 71680
#define SRED (SBUF + 2 * BUFSZ)
#define ATT_SMEM (SRED + 1024)

__global__ __launch_bounds__(256, 1) void attn_kernel() {
  extern __shared__ __align__(16) char smem[];
  const u32 sb = smem_u32(smem);

  const int tid = threadIdx.x;
  const int w = tid >> 5;
  const int lane = tid & 31;
  const int g = lane >> 2;
  const int t = lane & 3;
  const int rg = w & 3;
  const int kh = w >> 2;
  const int qb = blockIdx.x >> 1;
  const int half = blockIdx.x & 1;

  auto issue_K = [&](int tile, int b) {
    const u32 base = sb + SBUF + b * BUFSZ;
    const char* gkh = (const char*)g_Kh + (size_t)tile * 16384;
    const char* gkl = (const char*)g_Kl + (size_t)tile * 16384;
#pragma unroll
    for (int p = 0; p < 4; p++) {
      int idx = tid + 256 * p;
      int kr = idx >> 4, ks = idx & 15;
      int so = kr * RSTR + ks * 16;
      cp16(base + BKH + so, gkh + idx * 16);
      cp16(base + BKL + so, gkl + idx * 16);
    }
  };
  auto issue_V = [&](int tile, int b) {
    const u32 base = sb + SBUF + b * BUFSZ;
    const size_t vbase = (size_t)(tile >> 1) * 32768 + (size_t)(tile & 1) * 128;
    const char* gvh = (const char*)g_Vth + vbase;
    const char* gvl = (const char*)g_Vtl + vbase;
#pragma unroll
    for (int p = 0; p < 4; p++) {
      int idx = tid + 256 * p;
      int vd = idx >> 3, vs = idx & 7;
      int so = vd * VSTR + vs * 16;
      size_t voff = (size_t)vd * 256 + vs * 16;
      cp16(base + BVH + so, gvh + voff);
      cp16(base + BVL + so, gvl + voff);
    }
  };

  // S MMA block: s[mg][nf][4] += Q(rows) K(buf b)^T
  auto mma_S = [&](float s[2][4][4], int b) {
    const int oK = SBUF + b * BUFSZ + BKH + (32 * kh + g) * RSTR + t * 4;
#pragma unroll
    for (int kc = 0; kc < 8; kc++) {
      u32 ah[2][4], al[2][4];
#pragma unroll
      for (int mg = 0; mg < 2; mg++) {
        const int qo = SQH + (32 * rg + 16 * mg + g) * RSTR + t * 4 + kc * 32;
        ah[mg][0] = *(const u32*)(smem + qo);
        ah[mg][1] = *(const u32*)(smem + qo + 8 * RSTR);
        ah[mg][2] = *(const u32*)(smem + qo + 16);
        ah[mg][3] = *(const u32*)(smem + qo + 8 * RSTR + 16);
        al[mg][0] = *(const u32*)(smem + qo + QLO);
        al[mg][1] = *(const u32*)(smem + qo + QLO + 8 * RSTR);
        al[mg][2] = *(const u32*)(smem + qo + QLO + 16);
        al[mg][3] = *(const u32*)(smem + qo + QLO + 8 * RSTR + 16);
      }
#pragma unroll
      for (int nf = 0; nf < 4; nf++) {
        const int bo = oK + nf * 8 * RSTR + kc * 32;
        u32 bh0 = *(const u32*)(smem + bo);
        u32 bh1 = *(const u32*)(smem + bo + 16);
        u32 bl0 = *(const u32*)(smem + bo + 17408);
        u32 bl1 = *(const u32*)(smem + bo + 17408 + 16);
#pragma unroll
        for (int mg = 0; mg < 2; mg++) {
          mma16816(s[mg][nf], ah[mg][0], ah[mg][1], ah[mg][2], ah[mg][3], bh0, bh1);
          mma16816(s[mg][nf], al[mg][0], al[mg][1], al[mg][2], al[mg][3], bh0, bh1);
          mma16816(s[mg][nf], ah[mg][0], ah[mg][1], ah[mg][2], ah[mg][3], bl0, bl1);
        }
      }
    }
  };

  // ---- prologue: Q + tile0 (group 0), tile1 (group 1) ----
  {
    const char* gqh = (const char*)g_Qh + (size_t)qb * 32768;
    const char* gql = (const char*)g_Ql + (size_t)qb * 32768;
#pragma unroll
    for (int p = 0; p < 8; p++) {
      int idx = tid + 256 * p;
      int row = idx >> 4, sub = idx & 15;
      int so = row * RSTR + sub * 16;
      cp16(sb + SQH + so, gqh + idx * 16);
      cp16(sb + SQH + QLO + so, gql + idx * 16);
    }
    issue_K(half * 64, 0);
    issue_V(half * 64, 0);
    CP_COMMIT();
    issue_K(half * 64 + 1, 1);
    issue_V(half * 64 + 1, 1);
    CP_COMMIT();
  }

  float o[2][16][4];
#pragma unroll
  for (int mg = 0; mg < 2; mg++)
#pragma unroll
    for (int dg = 0; dg < 16; dg++)
#pragma unroll
      for (int j = 0; j < 4; j++) o[mg][dg][j] = 0.0f;
  float m_[2][2], l_[2][2];
#pragma unroll
  for (int mg = 0; mg < 2; mg++) {
    m_[mg][0] = -1e30f; m_[mg][1] = -1e30f;
    l_[mg][0] = 0.0f;   l_[mg][1] = 0.0f;
  }

  // ---- S(0) (group 0 done; group 1 still in flight) ----
  float s[2][4][4];
  CP_WAIT1();
  __syncthreads();
#pragma unroll
  for (int mg = 0; mg < 2; mg++)
#pragma unroll
    for (int nf = 0; nf < 4; nf++)
#pragma unroll
      for (int j = 0; j < 4; j++) s[mg][nf][j] = 0.0f;
  mma_S(s, 0);

#pragma unroll 1
  for (int it = 0; it < 64; ++it) {
    const int tt = half * 64 + it;

    // ---- softmax on s (tile it), log2 domain ----
    float alpha[2][2];
#pragma unroll
    for (int mg = 0; mg < 2; mg++) {
      float mt0 = -1e30f, mt1 = -1e30f;
#pragma unroll
      for (int nf = 0; nf < 4; nf++) {
        mt0 = fmaxf(mt0, fmaxf(s[mg][nf][0], s[mg][nf][1]));
        mt1 = fmaxf(mt1, fmaxf(s[mg][nf][2], s[mg][nf][3]));
      }
#pragma unroll
      for (int off = 1; off <= 2; off <<= 1) {
        mt0 = fmaxf(mt0, __shfl_xor_sync(0xffffffffu, mt0, off));
        mt1 = fmaxf(mt1, __shfl_xor_sync(0xffffffffu, mt1, off));
      }
      const float mn0 = fmaxf(m_[mg][0], mt0), mn1 = fmaxf(m_[mg][1], mt1);
      alpha[mg][0] = ex2(m_[mg][0] - mn0);
      alpha[mg][1] = ex2(m_[mg][1] - mn1);
      m_[mg][0] = mn0; m_[mg][1] = mn1;

      float sum0 = 0.0f, sum1 = 0.0f;
#pragma unroll
      for (int nf = 0; nf < 4; nf++) {
        s[mg][nf][0] = ex2(s[mg][nf][0] - mn0); sum0 += s[mg][nf][0];
        s[mg][nf][1] = ex2(s[mg][nf][1] - mn0); sum0 += s[mg][nf][1];
        s[mg][nf][2] = ex2(s[mg][nf][2] - mn1); sum1 += s[mg][nf][2];
        s[mg][nf][3] = ex2(s[mg][nf][3] - mn1); sum1 += s[mg][nf][3];
      }
#pragma unroll
      for (int off = 1; off <= 2; off <<= 1) {
        sum0 += __shfl_xor_sync(0xffffffffu, sum0, off);
        sum1 += __shfl_xor_sync(0xffffffffu, sum1, off);
      }
      l_[mg][0] = l_[mg][0] * alpha[mg][0] + sum0;
      l_[mg][1] = l_[mg][1] * alpha[mg][1] + sum1;
    }

    // ---- pack P (both k16 steps); after this s is dead ----
    u32 ph[2][2][4], pl[2][2][4];
#pragma unroll
    for (int c = 0; c < 2; c++)
#pragma unroll
      for (int mg = 0; mg < 2; mg++) {
        float e[8] = { s[mg][2*c][0],   s[mg][2*c][1],   s[mg][2*c][2],   s[mg][2*c][3],
                       s[mg][2*c+1][0], s[mg][2*c+1][1], s[mg][2*c+1][2], s[mg][2*c+1][3] };
        const int map[4][2] = {{0,1},{2,3},{4,5},{6,7}};
#pragma unroll
        for (int q = 0; q < 4; q++) {
          float x0 = e[map[q][0]], x1 = e[map[q][1]];
          u32 hp = cvt2(x1, x0);
          float h0 = __uint_as_float(hp << 16);
          float h1 = __uint_as_float(hp & 0xffff0000u);
          ph[c][mg][q] = hp;
          pl[c][mg][q] = cvt2(x1 - h1, x0 - h0);
        }
      }

    // ---- prefetch S(it+1) into the freed s registers ----
    if (it < 63) {
      CP_WAIT0();          // group (it+1) committed one full iteration ago
      __syncthreads();
#pragma unroll
      for (int mg = 0; mg < 2; mg++)
#pragma unroll
        for (int nf = 0; nf < 4; nf++)
#pragma unroll
          for (int j = 0; j < 4; j++) s[mg][nf][j] = 0.0f;
      mma_S(s, (it + 1) & 1);
    }

    // ---- rescale O (conditional) ----
    if (__any_sync(0xffffffffu,
                   (alpha[0][0] != 1.0f) | (alpha[0][1] != 1.0f) |
                   (alpha[1][0] != 1.0f) | (alpha[1][1] != 1.0f))) {
#pragma unroll
      for (int mg = 0; mg < 2; mg++)
#pragma unroll
        for (int dg = 0; dg < 16; dg++) {
          o[mg][dg][0] *= alpha[mg][0]; o[mg][dg][1] *= alpha[mg][0];
          o[mg][dg][2] *= alpha[mg][1]; o[mg][dg][3] *= alpha[mg][1];
        }
    }

    // ---- PV(it) ----
    const int bb = SBUF + (it & 1) * BUFSZ;
#pragma unroll
    for (int c = 0; c < 2; c++) {
      const int oV = bb + BVH + g * VSTR + t * 4 + kh * 64 + c * 32;
#pragma unroll
      for (int dg = 0; dg < 16; dg++) {
        const int vb = oV + dg * 8 * VSTR;
        u32 vh0 = *(const u32*)(smem + vb);
        u32 vh1 = *(const u32*)(smem + vb + 16);
        u32 vl0 = *(const u32*)(smem + vb + 18432);
        u32 vl1 = *(const u32*)(smem + vb + 18432 + 16);
#pragma unroll
        for (int mg = 0; mg < 2; mg++) {
          mma16816(o[mg][dg], ph[c][mg][0], ph[c][mg][1], ph[c][mg][2], ph[c][mg][3], vh0, vh1);
          mma16816(o[mg][dg], pl[c][mg][0], pl[c][mg][1], pl[c][mg][2], pl[c][mg][3], vh0, vh1);
          mma16816(o[mg][dg], ph[c][mg][0], ph[c][mg][1], ph[c][mg][2], ph[c][mg][3], vl0, vl1);
        }
      }
    }

    __syncthreads();   // buffer it&1 fully consumed; S(it+1) reads done
    if (it < 62) {
      issue_K(tt + 2, it & 1);
      issue_V(tt + 2, it & 1);
      CP_COMMIT();
    }
  }

  // ---- epilogue: merge kh=0/kh=1 (log2 domain), write half-partial to gmem ----
  __syncthreads();
  float* Ob = (float*)(smem + SBUF);
  float* marr = (float*)(smem + SRED);
  float* larr = marr + 128;
  if (kh == 0) {
#pragma unroll
    for (int mg = 0; mg < 2; mg++) {
      int r0 = 32 * rg + 16 * mg + g;
#pragma unroll
      for (int dg = 0; dg < 16; dg++) {
        int c0 = 8 * dg + 2 * t;
        Ob[r0 * 128 + c0]           = o[mg][dg][0];
        Ob[r0 * 128 + c0 + 1]       = o[mg][dg][1];
        Ob[(r0 + 8) * 128 + c0]     = o[mg][dg][2];
        Ob[(r0 + 8) * 128 + c0 + 1] = o[mg][dg][3];
      }
      if (t == 0) {
        marr[r0] = m_[mg][0];     larr[r0] = l_[mg][0];
        marr[r0 + 8] = m_[mg][1]; larr[r0 + 8] = l_[mg][1];
      }
    }
  }
  __syncthreads();
  if (kh == 1) {
    float* gop = &g_Op[half][(size_t)(qb * 128) * D_HEAD];
#pragma unroll
    for (int mg = 0; mg < 2; mg++) {
      int r0 = 32 * rg + 16 * mg + g;
#pragma unroll
      for (int hh = 0; hh < 2; hh++) {
        int r = r0 + 8 * hh;
        float pm = marr[r], pL = larr[r];
        float M = fmaxf(m_[mg][hh], pm);
        float ws = ex2(m_[mg][hh] - M), wo = ex2(pm - M);
        float lm = ws * l_[mg][hh] + wo * pL;
        if (t == 0) {
          g_m[half][qb * 128 + r] = M;
          g_l[half][qb * 128 + r] = lm;
        }
#pragma unroll
        for (int dg = 0; dg < 16; dg++) {
          int c0 = 8 * dg + 2 * t;
          float v0 = ws * o[mg][dg][2 * hh]     + wo * Ob[r * 128 + c0];
          float v1 = ws * o[mg][dg][2 * hh + 1] + wo * Ob[r * 128 + c0 + 1];
          *(float2*)&gop[(size_t)r * D_HEAD + c0] = make_float2(v0, v1);
        }
      }
    }
  }
}

// ---------------------------------------------------------------------------
// Split-K combine: out = (w0*O0 + w1*O1) / (w0*l0 + w1*l1)  (log2 domain m)
// ---------------------------------------------------------------------------
__global__ __launch_bounds__(256) void combine_kernel(float* __restrict__ out) {
  int idx = blockIdx.x * 256 + threadIdx.x;
  int r = idx >> 7;
  float m0 = g_m[0][r], m1 = g_m[1][r];
  float M = fmaxf(m0, m1);
  float w0 = ex2(m0 - M), w1 = ex2(m1 - M);
  float denom = w0 * g_l[0][r] + w1 * g_l[1][r];
  out[idx] = (w0 * g_Op[0][idx] + w1 * g_Op[1][idx]) / denom;
}

// ---------------------------------------------------------------------------
extern "C" void kernel_launch(void* const* d_in, const int* in_sizes, int n_in,
                              void* d_out, int out_size) {
  const float* x  = (const float*)d_in[0];
  const float* Wq = (const float*)d_in[1];
  const float* Wk = (const float*)d_in[2];
  const float* Wv = (const float*)d_in[3];
  float* out = (float*)d_out;

  cudaFuncSetAttribute(attn_kernel,
                       cudaFuncAttributeMaxDynamicSharedMemorySize, ATT_SMEM);
  cudaFuncSetAttribute(proj_mma_kernel,
                       cudaFuncAttributeMaxDynamicSharedMemorySize, PROJ_SMEM);

  split_x_kernel<<<(N_TOK * D_IN) / 2048, 256>>>(x);
  split_w_kernel<<<dim3((D_HEAD * D_IN) / 2048, 3), 256>>>(Wq, Wk, Wv);
  proj_mma_kernel<<<dim3(N_TOK / 128, 3), 256, PROJ_SMEM>>>();
  attn_kernel<<<128, 256, ATT_SMEM>>>();
  combine_kernel<<<(N_TOK * D_HEAD) / 256, 256>>>(out);
}

// round 13
// speedup vs baseline: 1.1189x; 1.1189x over previous
#include <cuda_runtime.h>
#include <cuda_bf16.h>
#include <math.h>
#include <stdint.h>

#define N_TOK 8192
#define D_IN  1024
#define D_HEAD 128

typedef uint32_t u32;

// ---------------------------------------------------------------------------
// Device-global scratch.
// ---------------------------------------------------------------------------
__device__ __align__(16) __nv_bfloat16 g_Xh[(size_t)N_TOK * D_IN];
__device__ __align__(16) __nv_bfloat16 g_Xl[(size_t)N_TOK * D_IN];
__device__ __align__(16) __nv_bfloat16 g_Wh[3 * D_HEAD * D_IN];
__device__ __align__(16) __nv_bfloat16 g_Wl[3 * D_HEAD * D_IN];
__device__ __align__(16) __nv_bfloat16 g_Qh[N_TOK * D_HEAD];
__device__ __align__(16) __nv_bfloat16 g_Ql[N_TOK * D_HEAD];
__device__ __align__(16) __nv_bfloat16 g_Kh[N_TOK * D_HEAD];
__device__ __align__(16) __nv_bfloat16 g_Kl[N_TOK * D_HEAD];
__device__ __align__(16) __nv_bfloat16 g_Vth[N_TOK * D_HEAD];
__device__ __align__(16) __nv_bfloat16 g_Vtl[N_TOK * D_HEAD];
// split-K partials (unnormalized O, per key-half) + log2-domain m,l
__device__ float g_Op[2][(size_t)N_TOK * D_HEAD];
__device__ float g_m[2][N_TOK];
__device__ float g_l[2][N_TOK];

__device__ __forceinline__ void split_bf16(float v, __nv_bfloat16& h, __nv_bfloat16& l) {
  h = __float2bfloat16(v);
  l = __float2bfloat16(v - __bfloat162float(h));
}

__device__ __forceinline__ u32 smem_u32(const void* p) {
  u32 a;
  asm("{ .reg .u64 t; cvta.to.shared.u64 t, %1; cvt.u32.u64 %0, t; }" : "=r"(a) : "l"(p));
  return a;
}
__device__ __forceinline__ void cp16(u32 dst, const void* src) {
  asm volatile("cp.async.cg.shared.global [%0], [%1], 16;" :: "r"(dst), "l"(src));
}
#define CP_COMMIT() asm volatile("cp.async.commit_group;" ::: "memory")
#define CP_WAIT0()  asm volatile("cp.async.wait_group 0;" ::: "memory")
#define CP_WAIT1()  asm volatile("cp.async.wait_group 1;" ::: "memory")

// m16n8k16 row.col bf16 -> f32 (HMMA; portable PTX)
__device__ __forceinline__ void mma16816(float* d, u32 a0, u32 a1, u32 a2, u32 a3,
                                         u32 b0, u32 b1) {
  asm volatile(
      "mma.sync.aligned.m16n8k16.row.col.f32.bf16.bf16.f32 "
      "{%0,%1,%2,%3}, {%4,%5,%6,%7}, {%8,%9}, {%0,%1,%2,%3};"
      : "+f"(d[0]), "+f"(d[1]), "+f"(d[2]), "+f"(d[3])
      : "r"(a0), "r"(a1), "r"(a2), "r"(a3), "r"(b0), "r"(b1));
}
__device__ __forceinline__ u32 cvt2(float hi, float lo) {
  u32 d;
  asm("cvt.rn.bf16x2.f32 %0, %1, %2;" : "=r"(d) : "f"(hi), "f"(lo));
  return d;
}
// fast 2^x (softmax runs in log2 domain; 1/ln2 folded into Q scale)
__device__ __forceinline__ float ex2(float x) {
  float y;
  asm("ex2.approx.f32 %0, %1;" : "=f"(y) : "f"(x));
  return y;
}

// ---------------------------------------------------------------------------
// Split kernels: fp32 -> bf16 hi/lo.
// ---------------------------------------------------------------------------
__device__ __forceinline__ void split8_store(const float* v, __nv_bfloat16* dh,
                                             __nv_bfloat16* dl) {
  u32 hw[4], lw[4];
#pragma unroll
  for (int j = 0; j < 4; j++) {
    __nv_bfloat16 h0, l0, h1, l1;
    split_bf16(v[2 * j], h0, l0);
    split_bf16(v[2 * j + 1], h1, l1);
    hw[j] = ((u32)__bfloat16_as_ushort(h1) << 16) | __bfloat16_as_ushort(h0);
    lw[j] = ((u32)__bfloat16_as_ushort(l1) << 16) | __bfloat16_as_ushort(l0);
  }
  *(uint4*)dh = make_uint4(hw[0], hw[1], hw[2], hw[3]);
  *(uint4*)dl = make_uint4(lw[0], lw[1], lw[2], lw[3]);
}

__global__ __launch_bounds__(256) void split_x_kernel(const float* __restrict__ X) {
  size_t i = ((size_t)blockIdx.x * 256 + threadIdx.x) * 8;
  float4 f0 = *(const float4*)&X[i];
  float4 f1 = *(const float4*)&X[i + 4];
  float v[8] = {f0.x, f0.y, f0.z, f0.w, f1.x, f1.y, f1.z, f1.w};
  split8_store(v, &g_Xh[i], &g_Xl[i]);
}

__global__ __launch_bounds__(256) void split_w_kernel(
    const float* __restrict__ Wq, const float* __restrict__ Wk,
    const float* __restrict__ Wv) {
  const int y = blockIdx.y;
  const float* W = (y == 0) ? Wq : (y == 1 ? Wk : Wv);
  size_t i = ((size_t)blockIdx.x * 256 + threadIdx.x) * 8;
  float4 f0 = *(const float4*)&W[i];
  float4 f1 = *(const float4*)&W[i + 4];
  float v[8] = {f0.x, f0.y, f0.z, f0.w, f1.x, f1.y, f1.z, f1.w};
  size_t o = (size_t)y * D_HEAD * D_IN + i;
  split8_store(v, &g_Wh[o], &g_Wl[o]);
}

// ---------------------------------------------------------------------------
// HMMA projection v2: BM=64, BN=128, grid (128, 3), 2 CTAs/SM.
// 8 warps = 4 row-groups (mw: 16 rows) x 2 col-halves (nh: 64 cols).
// Double-buffered BK=32 chunks; smem 30.7KB/stage.
// ---------------------------------------------------------------------------
#define PSTR 80
#define PXH 0
#define PXL 5120
#define PWH 10240
#define PWL 20480
#define PSTAGE 30720
#define PROJ_SMEM (2 * PSTAGE)

__global__ __launch_bounds__(256, 2) void proj_mma_kernel() {
  extern __shared__ __align__(16) char psm[];
  const u32 pb = smem_u32(psm);

  const int y = blockIdx.y;
  const int bm = blockIdx.x;            // 64-row block
  const int tid = threadIdx.x;
  const int w = tid >> 5;
  const int lane = tid & 31;
  const int g = lane >> 2;
  const int t = lane & 3;
  const int mw = w & 3;                 // row group (16 rows)
  const int nh = w >> 2;                // col half (64 cols)

  const char* xh = (const char*)g_Xh;
  const char* xl = (const char*)g_Xl;
  const char* wh = (const char*)(g_Wh + (size_t)y * D_HEAD * D_IN);
  const char* wl = (const char*)(g_Wl + (size_t)y * D_HEAD * D_IN);

  auto issue_chunk = [&](int kc32, int st) {
    const u32 base = pb + st * PSTAGE;
    const int k0 = kc32 * 32;
    // X: 64 rows x 32 bf16 hi/lo = 256 x 16B each
    {
      int row = tid >> 2, sub = tid & 3;
      int so = row * PSTR + sub * 16;
      size_t xoff = ((size_t)(bm * 64 + row) * D_IN + k0) * 2 + sub * 16;
      cp16(base + PXH + so, xh + xoff);
      cp16(base + PXL + so, xl + xoff);
    }
    // W: 128 rows x 32 bf16 hi/lo = 512 x 16B each
#pragma unroll
    for (int p = 0; p < 2; p++) {
      int idx = tid + 256 * p;
      int row = idx >> 2, sub = idx & 3;
      int so = row * PSTR + sub * 16;
      size_t woff = ((size_t)row * D_IN + k0) * 2 + sub * 16;
      cp16(base + PWH + so, wh + woff);
      cp16(base + PWL + so, wl + woff);
    }
  };

  float o[8][4];
#pragma unroll
  for (int i = 0; i < 8; i++)
#pragma unroll
    for (int j = 0; j < 4; j++) o[i][j] = 0.0f;

  issue_chunk(0, 0);
  CP_COMMIT();

#pragma unroll 1
  for (int kc32 = 0; kc32 < 32; kc32++) {
    if (kc32 < 31) {
      issue_chunk(kc32 + 1, (kc32 + 1) & 1);
      CP_COMMIT();
      CP_WAIT1();
    } else {
      CP_WAIT0();
    }
    __syncthreads();

    const char* sm = psm + (kc32 & 1) * PSTAGE;
    const int oX = (16 * mw + g) * PSTR + t * 4;
#pragma unroll
    for (int kc = 0; kc < 2; kc++) {
      const int qo = oX + kc * 32;
      u32 ah0 = *(const u32*)(sm + PXH + qo);
      u32 ah1 = *(const u32*)(sm + PXH + qo + 8 * PSTR);
      u32 ah2 = *(const u32*)(sm + PXH + qo + 16);
      u32 ah3 = *(const u32*)(sm + PXH + qo + 8 * PSTR + 16);
      u32 al0 = *(const u32*)(sm + PXL + qo);
      u32 al1 = *(const u32*)(sm + PXL + qo + 8 * PSTR);
      u32 al2 = *(const u32*)(sm + PXL + qo + 16);
      u32 al3 = *(const u32*)(sm + PXL + qo + 8 * PSTR + 16);
#pragma unroll
      for (int nf = 0; nf < 8; nf++) {
        const int bo = (64 * nh + 8 * nf + g) * PSTR + t * 4 + kc * 32;
        u32 bh0 = *(const u32*)(sm + PWH + bo);
        u32 bh1 = *(const u32*)(sm + PWH + bo + 16);
        float* d = o[nf];
        mma16816(d, ah0, ah1, ah2, ah3, bh0, bh1);
        mma16816(d, al0, al1, al2, al3, bh0, bh1);
        u32 bl0 = *(const u32*)(sm + PWL + bo);
        u32 bl1 = *(const u32*)(sm + PWL + bo + 16);
        mma16816(d, ah0, ah1, ah2, ah3, bl0, bl1);
      }
    }
    __syncthreads();
  }

  // Q scaled by sqrt(128)/ln(2): softmax runs in log2 domain.
  const float scale = 16.32223134f;
#pragma unroll
  for (int nf = 0; nf < 8; nf++) {
    int c0 = 64 * nh + 8 * nf + 2 * t;
    int R0 = bm * 64 + 16 * mw + g;
#pragma unroll
    for (int q = 0; q < 4; q++) {
      int R = R0 + (q >> 1) * 8;
      int c = c0 + (q & 1);
      float v = o[nf][q];
      __nv_bfloat16 h, l;
      if (y == 0) {
        split_bf16(v * scale, h, l);
        g_Qh[(size_t)R * D_HEAD + c] = h;
        g_Ql[(size_t)R * D_HEAD + c] = l;
      } else if (y == 1) {
        split_bf16(v, h, l);
        g_Kh[(size_t)R * D_HEAD + c] = h;
        g_Kl[(size_t)R * D_HEAD + c] = l;
      } else {
        split_bf16(v, h, l);
        size_t idx = (size_t)(R >> 7) * 16384 + (size_t)c * 128 + (R & 127);
        g_Vth[idx] = h;
        g_Vtl[idx] = l;
      }
    }
  }
}

// ---------------------------------------------------------------------------
// Flash kernel v3 (R11 champion, verbatim): BM=128, BN=64, warp tile 32x32,
// CTA split-K over key halves. grid = 128, 256 threads, 8 warps = rg4 x kh2.
// ---------------------------------------------------------------------------
#define RSTR 272
#define VSTR 144
#define SQH 0
#define QLO 34816
#define SBUF 69632
#define BKH 0
#define BKL 17408
#define BVH 34816
#define BVL 53248
#define BUFSZ 71680
#define SRED (SBUF + 2 * BUFSZ)
#define ATT_SMEM (SRED + 1024)

__global__ __launch_bounds__(256, 1) void attn_kernel() {
  extern __shared__ __align__(16) char smem[];
  const u32 sb = smem_u32(smem);

  const int tid = threadIdx.x;
  const int w = tid >> 5;
  const int lane = tid & 31;
  const int g = lane >> 2;
  const int t = lane & 3;
  const int rg = w & 3;
  const int kh = w >> 2;
  const int qb = blockIdx.x >> 1;
  const int half = blockIdx.x & 1;

  auto issue_K = [&](int tile, int b) {
    const u32 base = sb + SBUF + b * BUFSZ;
    const char* gkh = (const char*)g_Kh + (size_t)tile * 16384;
    const char* gkl = (const char*)g_Kl + (size_t)tile * 16384;
#pragma unroll
    for (int p = 0; p < 4; p++) {
      int idx = tid + 256 * p;
      int kr = idx >> 4, ks = idx & 15;
      int so = kr * RSTR + ks * 16;
      cp16(base + BKH + so, gkh + idx * 16);
      cp16(base + BKL + so, gkl + idx * 16);
    }
  };
  auto issue_V = [&](int tile, int b) {
    const u32 base = sb + SBUF + b * BUFSZ;
    const size_t vbase = (size_t)(tile >> 1) * 32768 + (size_t)(tile & 1) * 128;
    const char* gvh = (const char*)g_Vth + vbase;
    const char* gvl = (const char*)g_Vtl + vbase;
#pragma unroll
    for (int p = 0; p < 4; p++) {
      int idx = tid + 256 * p;
      int vd = idx >> 3, vs = idx & 7;
      int so = vd * VSTR + vs * 16;
      size_t voff = (size_t)vd * 256 + vs * 16;
      cp16(base + BVH + so, gvh + voff);
      cp16(base + BVL + so, gvl + voff);
    }
  };

  // ---- prologue: Q (128 rows hi+lo) + first two tiles ----
  {
    const char* gqh = (const char*)g_Qh + (size_t)qb * 32768;
    const char* gql = (const char*)g_Ql + (size_t)qb * 32768;
#pragma unroll
    for (int p = 0; p < 8; p++) {
      int idx = tid + 256 * p;
      int row = idx >> 4, sub = idx & 15;
      int so = row * RSTR + sub * 16;
      cp16(sb + SQH + so, gqh + idx * 16);
      cp16(sb + SQH + QLO + so, gql + idx * 16);
    }
    issue_K(half * 64, 0);
    issue_V(half * 64, 0);
    CP_COMMIT();
    issue_K(half * 64 + 1, 1);
    issue_V(half * 64 + 1, 1);
    CP_COMMIT();
  }

  float o[2][16][4];
#pragma unroll
  for (int mg = 0; mg < 2; mg++)
#pragma unroll
    for (int dg = 0; dg < 16; dg++)
#pragma unroll
      for (int j = 0; j < 4; j++) o[mg][dg][j] = 0.0f;
  float m_[2][2], l_[2][2];
#pragma unroll
  for (int mg = 0; mg < 2; mg++) {
    m_[mg][0] = -1e30f; m_[mg][1] = -1e30f;
    l_[mg][0] = 0.0f;   l_[mg][1] = 0.0f;
  }

#pragma unroll 1
  for (int it = 0; it < 64; ++it) {
    const int tt = half * 64 + it;
    if (it < 63) CP_WAIT1(); else CP_WAIT0();
    __syncthreads();
    const int bb = SBUF + (it & 1) * BUFSZ;

    // ---- S = Q K^T : s[mg][nf][4], 192 HMMA ----
    float s[2][4][4];
#pragma unroll
    for (int mg = 0; mg < 2; mg++)
#pragma unroll
      for (int nf = 0; nf < 4; nf++)
#pragma unroll
        for (int j = 0; j < 4; j++) s[mg][nf][j] = 0.0f;

    const int oK = bb + BKH + (32 * kh + g) * RSTR + t * 4;
#pragma unroll
    for (int kc = 0; kc < 8; kc++) {
      u32 ah[2][4], al[2][4];
#pragma unroll
      for (int mg = 0; mg < 2; mg++) {
        const int qo = SQH + (32 * rg + 16 * mg + g) * RSTR + t * 4 + kc * 32;
        ah[mg][0] = *(const u32*)(smem + qo);
        ah[mg][1] = *(const u32*)(smem + qo + 8 * RSTR);
        ah[mg][2] = *(const u32*)(smem + qo + 16);
        ah[mg][3] = *(const u32*)(smem + qo + 8 * RSTR + 16);
        al[mg][0] = *(const u32*)(smem + qo + QLO);
        al[mg][1] = *(const u32*)(smem + qo + QLO + 8 * RSTR);
        al[mg][2] = *(const u32*)(smem + qo + QLO + 16);
        al[mg][3] = *(const u32*)(smem + qo + QLO + 8 * RSTR + 16);
      }
#pragma unroll
      for (int nf = 0; nf < 4; nf++) {
        const int bo = oK + nf * 8 * RSTR + kc * 32;
        u32 bh0 = *(const u32*)(smem + bo);
        u32 bh1 = *(const u32*)(smem + bo + 16);
        u32 bl0 = *(const u32*)(smem + bo + 17408);
        u32 bl1 = *(const u32*)(smem + bo + 17408 + 16);
#pragma unroll
        for (int mg = 0; mg < 2; mg++) {
          mma16816(s[mg][nf], ah[mg][0], ah[mg][1], ah[mg][2], ah[mg][3], bh0, bh1);
          mma16816(s[mg][nf], al[mg][0], al[mg][1], al[mg][2], al[mg][3], bh0, bh1);
          mma16816(s[mg][nf], ah[mg][0], ah[mg][1], ah[mg][2], ah[mg][3], bl0, bl1);
        }
      }
    }

    // ---- online softmax (log2 domain), per mg ----
    float alpha[2][2];
#pragma unroll
    for (int mg = 0; mg < 2; mg++) {
      float mt0 = -1e30f, mt1 = -1e30f;
#pragma unroll
      for (int nf = 0; nf < 4; nf++) {
        mt0 = fmaxf(mt0, fmaxf(s[mg][nf][0], s[mg][nf][1]));
        mt1 = fmaxf(mt1, fmaxf(s[mg][nf][2], s[mg][nf][3]));
      }
#pragma unroll
      for (int off = 1; off <= 2; off <<= 1) {
        mt0 = fmaxf(mt0, __shfl_xor_sync(0xffffffffu, mt0, off));
        mt1 = fmaxf(mt1, __shfl_xor_sync(0xffffffffu, mt1, off));
      }
      const float mn0 = fmaxf(m_[mg][0], mt0), mn1 = fmaxf(m_[mg][1], mt1);
      alpha[mg][0] = ex2(m_[mg][0] - mn0);
      alpha[mg][1] = ex2(m_[mg][1] - mn1);
      m_[mg][0] = mn0; m_[mg][1] = mn1;

      float sum0 = 0.0f, sum1 = 0.0f;
#pragma unroll
      for (int nf = 0; nf < 4; nf++) {
        s[mg][nf][0] = ex2(s[mg][nf][0] - mn0); sum0 += s[mg][nf][0];
        s[mg][nf][1] = ex2(s[mg][nf][1] - mn0); sum0 += s[mg][nf][1];
        s[mg][nf][2] = ex2(s[mg][nf][2] - mn1); sum1 += s[mg][nf][2];
        s[mg][nf][3] = ex2(s[mg][nf][3] - mn1); sum1 += s[mg][nf][3];
      }
#pragma unroll
      for (int off = 1; off <= 2; off <<= 1) {
        sum0 += __shfl_xor_sync(0xffffffffu, sum0, off);
        sum1 += __shfl_xor_sync(0xffffffffu, sum1, off);
      }
      l_[mg][0] = l_[mg][0] * alpha[mg][0] + sum0;
      l_[mg][1] = l_[mg][1] * alpha[mg][1] + sum1;
    }

    // rescale O only if any max moved (ex2(0)==1.0 exactly)
    if (__any_sync(0xffffffffu,
                   (alpha[0][0] != 1.0f) | (alpha[0][1] != 1.0f) |
                   (alpha[1][0] != 1.0f) | (alpha[1][1] != 1.0f))) {
#pragma unroll
      for (int mg = 0; mg < 2; mg++)
#pragma unroll
        for (int dg = 0; dg < 16; dg++) {
          o[mg][dg][0] *= alpha[mg][0]; o[mg][dg][1] *= alpha[mg][0];
          o[mg][dg][2] *= alpha[mg][1]; o[mg][dg][3] *= alpha[mg][1];
        }
    }

    // ---- PV: per k16 step c, pack P hi/lo and accumulate, 192 HMMA ----
#pragma unroll
    for (int c = 0; c < 2; c++) {
      u32 ph[2][4], pl[2][4];
#pragma unroll
      for (int mg = 0; mg < 2; mg++) {
        float e[8] = { s[mg][2*c][0],   s[mg][2*c][1],   s[mg][2*c][2],   s[mg][2*c][3],
                       s[mg][2*c+1][0], s[mg][2*c+1][1], s[mg][2*c+1][2], s[mg][2*c+1][3] };
        const int map[4][2] = {{0,1},{2,3},{4,5},{6,7}};
#pragma unroll
        for (int q = 0; q < 4; q++) {
          float x0 = e[map[q][0]], x1 = e[map[q][1]];
          u32 hp = cvt2(x1, x0);
          float h0 = __uint_as_float(hp << 16);
          float h1 = __uint_as_float(hp & 0xffff0000u);
          ph[mg][q] = hp;
          pl[mg][q] = cvt2(x1 - h1, x0 - h0);
        }
      }
      const int oV = bb + BVH + g * VSTR + t * 4 + kh * 64 + c * 32;
#pragma unroll
      for (int dg = 0; dg < 16; dg++) {
        const int vb = oV + dg * 8 * VSTR;
        u32 vh0 = *(const u32*)(smem + vb);
        u32 vh1 = *(const u32*)(smem + vb + 16);
        u32 vl0 = *(const u32*)(smem + vb + 18432);
        u32 vl1 = *(const u32*)(smem + vb + 18432 + 16);
#pragma unroll
        for (int mg = 0; mg < 2; mg++) {
          mma16816(o[mg][dg], ph[mg][0], ph[mg][1], ph[mg][2], ph[mg][3], vh0, vh1);
          mma16816(o[mg][dg], pl[mg][0], pl[mg][1], pl[mg][2], pl[mg][3], vh0, vh1);
          mma16816(o[mg][dg], ph[mg][0], ph[mg][1], ph[mg][2], ph[mg][3], vl0, vl1);
        }
      }
    }

    __syncthreads();   // buffer fully consumed
    if (it < 62) {
      issue_K(tt + 2, it & 1);
      issue_V(tt + 2, it & 1);
      CP_COMMIT();
    }
  }

  // ---- epilogue: merge kh=0/kh=1 (log2 domain), write half-partial to gmem ----
  __syncthreads();
  float* Ob = (float*)(smem + SBUF);
  float* marr = (float*)(smem + SRED);
  float* larr = marr + 128;
  if (kh == 0) {
#pragma unroll
    for (int mg = 0; mg < 2; mg++) {
      int r0 = 32 * rg + 16 * mg + g;
#pragma unroll
      for (int dg = 0; dg < 16; dg++) {
        int c0 = 8 * dg + 2 * t;
        Ob[r0 * 128 + c0]           = o[mg][dg][0];
        Ob[r0 * 128 + c0 + 1]       = o[mg][dg][1];
        Ob[(r0 + 8) * 128 + c0]     = o[mg][dg][2];
        Ob[(r0 + 8) * 128 + c0 + 1] = o[mg][dg][3];
      }
      if (t == 0) {
        marr[r0] = m_[mg][0];     larr[r0] = l_[mg][0];
        marr[r0 + 8] = m_[mg][1]; larr[r0 + 8] = l_[mg][1];
      }
    }
  }
  __syncthreads();
  if (kh == 1) {
    float* gop = &g_Op[half][(size_t)(qb * 128) * D_HEAD];
#pragma unroll
    for (int mg = 0; mg < 2; mg++) {
      int r0 = 32 * rg + 16 * mg + g;
#pragma unroll
      for (int hh = 0; hh < 2; hh++) {
        int r = r0 + 8 * hh;
        float pm = marr[r], pL = larr[r];
        float M = fmaxf(m_[mg][hh], pm);
        float ws = ex2(m_[mg][hh] - M), wo = ex2(pm - M);
        float lm = ws * l_[mg][hh] + wo * pL;
        if (t == 0) {
          g_m[half][qb * 128 + r] = M;
          g_l[half][qb * 128 + r] = lm;
        }
#pragma unroll
        for (int dg = 0; dg < 16; dg++) {
          int c0 = 8 * dg + 2 * t;
          float v0 = ws * o[mg][dg][2 * hh]     + wo * Ob[r * 128 + c0];
          float v1 = ws * o[mg][dg][2 * hh + 1] + wo * Ob[r * 128 + c0 + 1];
          *(float2*)&gop[(size_t)r * D_HEAD + c0] = make_float2(v0, v1);
        }
      }
    }
  }
}

// ---------------------------------------------------------------------------
// Split-K combine: out = (w0*O0 + w1*O1) / (w0*l0 + w1*l1)  (log2 domain m)
// ---------------------------------------------------------------------------
__global__ __launch_bounds__(256) void combine_kernel(float* __restrict__ out) {
  int idx = blockIdx.x * 256 + threadIdx.x;
  int r = idx >> 7;
  float m0 = g_m[0][r], m1 = g_m[1][r];
  float M = fmaxf(m0, m1);
  float w0 = ex2(m0 - M), w1 = ex2(m1 - M);
  float denom = w0 * g_l[0][r] + w1 * g_l[1][r];
  out[idx] = (w0 * g_Op[0][idx] + w1 * g_Op[1][idx]) / denom;
}

// ---------------------------------------------------------------------------
extern "C" void kernel_launch(void* const* d_in, const int* in_sizes, int n_in,
                              void* d_out, int out_size) {
  const float* x  = (const float*)d_in[0];
  const float* Wq = (const float*)d_in[1];
  const float* Wk = (const float*)d_in[2];
  const float* Wv = (const float*)d_in[3];
  float* out = (float*)d_out;

  cudaFuncSetAttribute(attn_kernel,
                       cudaFuncAttributeMaxDynamicSharedMemorySize, ATT_SMEM);
  cudaFuncSetAttribute(proj_mma_kernel,
                       cudaFuncAttributeMaxDynamicSharedMemorySize, PROJ_SMEM);

  split_x_kernel<<<(N_TOK * D_IN) / 2048, 256>>>(x);
  split_w_kernel<<<dim3((D_HEAD * D_IN) / 2048, 3), 256>>>(Wq, Wk, Wv);
  proj_mma_kernel<<<dim3(N_TOK / 64, 3), 256, PROJ_SMEM>>>();
  attn_kernel<<<128, 256, ATT_SMEM>>>();
  combine_kernel<<<(N_TOK * D_HEAD) / 256, 256>>>(out);
}

// round 14
// speedup vs baseline: 1.1223x; 1.0031x over previous
#include <cuda_runtime.h>
#include <cuda_bf16.h>
#include <math.h>
#include <stdint.h>

#define N_TOK 8192
#define D_IN  1024
#define D_HEAD 128

typedef uint32_t u32;

// ---------------------------------------------------------------------------
// Device-global scratch.
// ---------------------------------------------------------------------------
__device__ __align__(16) __nv_bfloat16 g_Xh[(size_t)N_TOK * D_IN];
__device__ __align__(16) __nv_bfloat16 g_Xl[(size_t)N_TOK * D_IN];
__device__ __align__(16) __nv_bfloat16 g_Wh[3 * D_HEAD * D_IN];
__device__ __align__(16) __nv_bfloat16 g_Wl[3 * D_HEAD * D_IN];
__device__ __align__(16) __nv_bfloat16 g_Qh[N_TOK * D_HEAD];
__device__ __align__(16) __nv_bfloat16 g_Ql[N_TOK * D_HEAD];
__device__ __align__(16) __nv_bfloat16 g_Kh[N_TOK * D_HEAD];
__device__ __align__(16) __nv_bfloat16 g_Kl[N_TOK * D_HEAD];
__device__ __align__(16) __nv_bfloat16 g_Vth[N_TOK * D_HEAD];
__device__ __align__(16) __nv_bfloat16 g_Vtl[N_TOK * D_HEAD];
// 16-way split-K partials (unnormalized O) + log2-domain m,l per key-chunk
__device__ float g_Op16[16][(size_t)N_TOK * D_HEAD];
__device__ float g_m16[16][N_TOK];
__device__ float g_l16[16][N_TOK];

__device__ __forceinline__ void split_bf16(float v, __nv_bfloat16& h, __nv_bfloat16& l) {
  h = __float2bfloat16(v);
  l = __float2bfloat16(v - __bfloat162float(h));
}

__device__ __forceinline__ u32 smem_u32(const void* p) {
  u32 a;
  asm("{ .reg .u64 t; cvta.to.shared.u64 t, %1; cvt.u32.u64 %0, t; }" : "=r"(a) : "l"(p));
  return a;
}
__device__ __forceinline__ void cp16(u32 dst, const void* src) {
  asm volatile("cp.async.cg.shared.global [%0], [%1], 16;" :: "r"(dst), "l"(src));
}
#define CP_COMMIT() asm volatile("cp.async.commit_group;" ::: "memory")
#define CP_WAIT0()  asm volatile("cp.async.wait_group 0;" ::: "memory")
#define CP_WAIT1()  asm volatile("cp.async.wait_group 1;" ::: "memory")

// m16n8k16 row.col bf16 -> f32 (HMMA; portable PTX)
__device__ __forceinline__ void mma16816(float* d, u32 a0, u32 a1, u32 a2, u32 a3,
                                         u32 b0, u32 b1) {
  asm volatile(
      "mma.sync.aligned.m16n8k16.row.col.f32.bf16.bf16.f32 "
      "{%0,%1,%2,%3}, {%4,%5,%6,%7}, {%8,%9}, {%0,%1,%2,%3};"
      : "+f"(d[0]), "+f"(d[1]), "+f"(d[2]), "+f"(d[3])
      : "r"(a0), "r"(a1), "r"(a2), "r"(a3), "r"(b0), "r"(b1));
}
__device__ __forceinline__ u32 cvt2(float hi, float lo) {
  u32 d;
  asm("cvt.rn.bf16x2.f32 %0, %1, %2;" : "=r"(d) : "f"(hi), "f"(lo));
  return d;
}
// fast 2^x (softmax runs in log2 domain; 1/ln2 folded into Q scale)
__device__ __forceinline__ float ex2(float x) {
  float y;
  asm("ex2.approx.f32 %0, %1;" : "=f"(y) : "f"(x));
  return y;
}

// ---------------------------------------------------------------------------
// Split kernels: fp32 -> bf16 hi/lo.
// ---------------------------------------------------------------------------
__device__ __forceinline__ void split8_store(const float* v, __nv_bfloat16* dh,
                                             __nv_bfloat16* dl) {
  u32 hw[4], lw[4];
#pragma unroll
  for (int j = 0; j < 4; j++) {
    __nv_bfloat16 h0, l0, h1, l1;
    split_bf16(v[2 * j], h0, l0);
    split_bf16(v[2 * j + 1], h1, l1);
    hw[j] = ((u32)__bfloat16_as_ushort(h1) << 16) | __bfloat16_as_ushort(h0);
    lw[j] = ((u32)__bfloat16_as_ushort(l1) << 16) | __bfloat16_as_ushort(l0);
  }
  *(uint4*)dh = make_uint4(hw[0], hw[1], hw[2], hw[3]);
  *(uint4*)dl = make_uint4(lw[0], lw[1], lw[2], lw[3]);
}

__global__ __launch_bounds__(256) void split_x_kernel(const float* __restrict__ X) {
  size_t i = ((size_t)blockIdx.x * 256 + threadIdx.x) * 8;
  float4 f0 = *(const float4*)&X[i];
  float4 f1 = *(const float4*)&X[i + 4];
  float v[8] = {f0.x, f0.y, f0.z, f0.w, f1.x, f1.y, f1.z, f1.w};
  split8_store(v, &g_Xh[i], &g_Xl[i]);
}

__global__ __launch_bounds__(256) void split_w_kernel(
    const float* __restrict__ Wq, const float* __restrict__ Wk,
    const float* __restrict__ Wv) {
  const int y = blockIdx.y;
  const float* W = (y == 0) ? Wq : (y == 1 ? Wk : Wv);
  size_t i = ((size_t)blockIdx.x * 256 + threadIdx.x) * 8;
  float4 f0 = *(const float4*)&W[i];
  float4 f1 = *(const float4*)&W[i + 4];
  float v[8] = {f0.x, f0.y, f0.z, f0.w, f1.x, f1.y, f1.z, f1.w};
  size_t o = (size_t)y * D_HEAD * D_IN + i;
  split8_store(v, &g_Wh[o], &g_Wl[o]);
}

// ---------------------------------------------------------------------------
// HMMA projection v2 (R13, unchanged): BM=64, BN=128, grid (128, 3), 2 CTAs/SM.
// ---------------------------------------------------------------------------
#define PSTR 80
#define PXH 0
#define PXL 5120
#define PWH 10240
#define PWL 20480
#define PSTAGE 30720
#define PROJ_SMEM (2 * PSTAGE)

__global__ __launch_bounds__(256, 2) void proj_mma_kernel() {
  extern __shared__ __align__(16) char psm[];
  const u32 pb = smem_u32(psm);

  const int y = blockIdx.y;
  const int bm = blockIdx.x;
  const int tid = threadIdx.x;
  const int w = tid >> 5;
  const int lane = tid & 31;
  const int g = lane >> 2;
  const int t = lane & 3;
  const int mw = w & 3;
  const int nh = w >> 2;

  const char* xh = (const char*)g_Xh;
  const char* xl = (const char*)g_Xl;
  const char* wh = (const char*)(g_Wh + (size_t)y * D_HEAD * D_IN);
  const char* wl = (const char*)(g_Wl + (size_t)y * D_HEAD * D_IN);

  auto issue_chunk = [&](int kc32, int st) {
    const u32 base = pb + st * PSTAGE;
    const int k0 = kc32 * 32;
    {
      int row = tid >> 2, sub = tid & 3;
      int so = row * PSTR + sub * 16;
      size_t xoff = ((size_t)(bm * 64 + row) * D_IN + k0) * 2 + sub * 16;
      cp16(base + PXH + so, xh + xoff);
      cp16(base + PXL + so, xl + xoff);
    }
#pragma unroll
    for (int p = 0; p < 2; p++) {
      int idx = tid + 256 * p;
      int row = idx >> 2, sub = idx & 3;
      int so = row * PSTR + sub * 16;
      size_t woff = ((size_t)row * D_IN + k0) * 2 + sub * 16;
      cp16(base + PWH + so, wh + woff);
      cp16(base + PWL + so, wl + woff);
    }
  };

  float o[8][4];
#pragma unroll
  for (int i = 0; i < 8; i++)
#pragma unroll
    for (int j = 0; j < 4; j++) o[i][j] = 0.0f;

  issue_chunk(0, 0);
  CP_COMMIT();

#pragma unroll 1
  for (int kc32 = 0; kc32 < 32; kc32++) {
    if (kc32 < 31) {
      issue_chunk(kc32 + 1, (kc32 + 1) & 1);
      CP_COMMIT();
      CP_WAIT1();
    } else {
      CP_WAIT0();
    }
    __syncthreads();

    const char* sm = psm + (kc32 & 1) * PSTAGE;
    const int oX = (16 * mw + g) * PSTR + t * 4;
#pragma unroll
    for (int kc = 0; kc < 2; kc++) {
      const int qo = oX + kc * 32;
      u32 ah0 = *(const u32*)(sm + PXH + qo);
      u32 ah1 = *(const u32*)(sm + PXH + qo + 8 * PSTR);
      u32 ah2 = *(const u32*)(sm + PXH + qo + 16);
      u32 ah3 = *(const u32*)(sm + PXH + qo + 8 * PSTR + 16);
      u32 al0 = *(const u32*)(sm + PXL + qo);
      u32 al1 = *(const u32*)(sm + PXL + qo + 8 * PSTR);
      u32 al2 = *(const u32*)(sm + PXL + qo + 16);
      u32 al3 = *(const u32*)(sm + PXL + qo + 8 * PSTR + 16);
#pragma unroll
      for (int nf = 0; nf < 8; nf++) {
        const int bo = (64 * nh + 8 * nf + g) * PSTR + t * 4 + kc * 32;
        u32 bh0 = *(const u32*)(sm + PWH + bo);
        u32 bh1 = *(const u32*)(sm + PWH + bo + 16);
        float* d = o[nf];
        mma16816(d, ah0, ah1, ah2, ah3, bh0, bh1);
        mma16816(d, al0, al1, al2, al3, bh0, bh1);
        u32 bl0 = *(const u32*)(sm + PWL + bo);
        u32 bl1 = *(const u32*)(sm + PWL + bo + 16);
        mma16816(d, ah0, ah1, ah2, ah3, bl0, bl1);
      }
    }
    __syncthreads();
  }

  const float scale = 16.32223134f;   // sqrt(128)/ln(2)
#pragma unroll
  for (int nf = 0; nf < 8; nf++) {
    int c0 = 64 * nh + 8 * nf + 2 * t;
    int R0 = bm * 64 + 16 * mw + g;
#pragma unroll
    for (int q = 0; q < 4; q++) {
      int R = R0 + (q >> 1) * 8;
      int c = c0 + (q & 1);
      float v = o[nf][q];
      __nv_bfloat16 h, l;
      if (y == 0) {
        split_bf16(v * scale, h, l);
        g_Qh[(size_t)R * D_HEAD + c] = h;
        g_Ql[(size_t)R * D_HEAD + c] = l;
      } else if (y == 1) {
        split_bf16(v, h, l);
        g_Kh[(size_t)R * D_HEAD + c] = h;
        g_Kl[(size_t)R * D_HEAD + c] = l;
      } else {
        split_bf16(v, h, l);
        size_t idx = (size_t)(R >> 7) * 16384 + (size_t)c * 128 + (R & 127);
        g_Vth[idx] = h;
        g_Vtl[idx] = l;
      }
    }
  }
}

// ---------------------------------------------------------------------------
// Persistent flash kernel: R11 inner loop, persistent scheduling shell.
// grid = #SMs. Work = 1024 units (64 qb x 16 chunks of 8 key-tiles), statically
// range-partitioned. Per unit: load Q(qb), run 8 tiles (R11 pipeline), kh-merge,
// write log2-domain partial (m, l, O) to g_*16[ch].
// ---------------------------------------------------------------------------
#define RSTR 272
#define VSTR 144
#define SQH 0
#define QLO 34816
#define SBUF 69632
#define BKH 0
#define BKL 17408
#define BVH 34816
#define BVL 53248
#define BUFSZ 71680
#define SRED (SBUF + 2 * BUFSZ)
#define ATT_SMEM (SRED + 1024)

__global__ __launch_bounds__(256, 1) void attn_kernel() {
  extern __shared__ __align__(16) char smem[];
  const u32 sb = smem_u32(smem);

  const int tid = threadIdx.x;
  const int w = tid >> 5;
  const int lane = tid & 31;
  const int g = lane >> 2;
  const int t = lane & 3;
  const int rg = w & 3;
  const int kh = w >> 2;

  auto issue_K = [&](int tile, int b) {
    const u32 base = sb + SBUF + b * BUFSZ;
    const char* gkh = (const char*)g_Kh + (size_t)tile * 16384;
    const char* gkl = (const char*)g_Kl + (size_t)tile * 16384;
#pragma unroll
    for (int p = 0; p < 4; p++) {
      int idx = tid + 256 * p;
      int kr = idx >> 4, ks = idx & 15;
      int so = kr * RSTR + ks * 16;
      cp16(base + BKH + so, gkh + idx * 16);
      cp16(base + BKL + so, gkl + idx * 16);
    }
  };
  auto issue_V = [&](int tile, int b) {
    const u32 base = sb + SBUF + b * BUFSZ;
    const size_t vbase = (size_t)(tile >> 1) * 32768 + (size_t)(tile & 1) * 128;
    const char* gvh = (const char*)g_Vth + vbase;
    const char* gvl = (const char*)g_Vtl + vbase;
#pragma unroll
    for (int p = 0; p < 4; p++) {
      int idx = tid + 256 * p;
      int vd = idx >> 3, vs = idx & 7;
      int so = vd * VSTR + vs * 16;
      size_t voff = (size_t)vd * 256 + vs * 16;
      cp16(base + BVH + so, gvh + voff);
      cp16(base + BVL + so, gvl + voff);
    }
  };

  const int nC = gridDim.x;
  const int c = blockIdx.x;
  const int u0 = (c * 1024) / nC;
  const int u1 = ((c + 1) * 1024) / nC;

#pragma unroll 1
  for (int u = u0; u < u1; ++u) {
    const int qb = u >> 4;
    const int ch = u & 15;
    const int t0 = ch * 8;

    // ---- unit prologue: Q(qb) + tiles t0 (group 0), t0+1 (group 1) ----
    {
      const char* gqh = (const char*)g_Qh + (size_t)qb * 32768;
      const char* gql = (const char*)g_Ql + (size_t)qb * 32768;
#pragma unroll
      for (int p = 0; p < 8; p++) {
        int idx = tid + 256 * p;
        int row = idx >> 4, sub = idx & 15;
        int so = row * RSTR + sub * 16;
        cp16(sb + SQH + so, gqh + idx * 16);
        cp16(sb + SQH + QLO + so, gql + idx * 16);
      }
      issue_K(t0, 0);
      issue_V(t0, 0);
      CP_COMMIT();
      issue_K(t0 + 1, 1);
      issue_V(t0 + 1, 1);
      CP_COMMIT();
    }

    float o[2][16][4];
#pragma unroll
    for (int mg = 0; mg < 2; mg++)
#pragma unroll
      for (int dg = 0; dg < 16; dg++)
#pragma unroll
        for (int j = 0; j < 4; j++) o[mg][dg][j] = 0.0f;
    float m_[2][2], l_[2][2];
#pragma unroll
    for (int mg = 0; mg < 2; mg++) {
      m_[mg][0] = -1e30f; m_[mg][1] = -1e30f;
      l_[mg][0] = 0.0f;   l_[mg][1] = 0.0f;
    }

#pragma unroll 1
    for (int it = 0; it < 8; ++it) {
      if (it < 7) CP_WAIT1(); else CP_WAIT0();
      __syncthreads();
      const int bb = SBUF + (it & 1) * BUFSZ;

      // ---- S = Q K^T : s[mg][nf][4], 192 HMMA ----
      float s[2][4][4];
#pragma unroll
      for (int mg = 0; mg < 2; mg++)
#pragma unroll
        for (int nf = 0; nf < 4; nf++)
#pragma unroll
          for (int j = 0; j < 4; j++) s[mg][nf][j] = 0.0f;

      const int oK = bb + BKH + (32 * kh + g) * RSTR + t * 4;
#pragma unroll
      for (int kc = 0; kc < 8; kc++) {
        u32 ah[2][4], al[2][4];
#pragma unroll
        for (int mg = 0; mg < 2; mg++) {
          const int qo = SQH + (32 * rg + 16 * mg + g) * RSTR + t * 4 + kc * 32;
          ah[mg][0] = *(const u32*)(smem + qo);
          ah[mg][1] = *(const u32*)(smem + qo + 8 * RSTR);
          ah[mg][2] = *(const u32*)(smem + qo + 16);
          ah[mg][3] = *(const u32*)(smem + qo + 8 * RSTR + 16);
          al[mg][0] = *(const u32*)(smem + qo + QLO);
          al[mg][1] = *(const u32*)(smem + qo + QLO + 8 * RSTR);
          al[mg][2] = *(const u32*)(smem + qo + QLO + 16);
          al[mg][3] = *(const u32*)(smem + qo + QLO + 8 * RSTR + 16);
        }
#pragma unroll
        for (int nf = 0; nf < 4; nf++) {
          const int bo = oK + nf * 8 * RSTR + kc * 32;
          u32 bh0 = *(const u32*)(smem + bo);
          u32 bh1 = *(const u32*)(smem + bo + 16);
          u32 bl0 = *(const u32*)(smem + bo + 17408);
          u32 bl1 = *(const u32*)(smem + bo + 17408 + 16);
#pragma unroll
          for (int mg = 0; mg < 2; mg++) {
            mma16816(s[mg][nf], ah[mg][0], ah[mg][1], ah[mg][2], ah[mg][3], bh0, bh1);
            mma16816(s[mg][nf], al[mg][0], al[mg][1], al[mg][2], al[mg][3], bh0, bh1);
            mma16816(s[mg][nf], ah[mg][0], ah[mg][1], ah[mg][2], ah[mg][3], bl0, bl1);
          }
        }
      }

      // ---- online softmax (log2 domain), per mg ----
      float alpha[2][2];
#pragma unroll
      for (int mg = 0; mg < 2; mg++) {
        float mt0 = -1e30f, mt1 = -1e30f;
#pragma unroll
        for (int nf = 0; nf < 4; nf++) {
          mt0 = fmaxf(mt0, fmaxf(s[mg][nf][0], s[mg][nf][1]));
          mt1 = fmaxf(mt1, fmaxf(s[mg][nf][2], s[mg][nf][3]));
        }
#pragma unroll
        for (int off = 1; off <= 2; off <<= 1) {
          mt0 = fmaxf(mt0, __shfl_xor_sync(0xffffffffu, mt0, off));
          mt1 = fmaxf(mt1, __shfl_xor_sync(0xffffffffu, mt1, off));
        }
        const float mn0 = fmaxf(m_[mg][0], mt0), mn1 = fmaxf(m_[mg][1], mt1);
        alpha[mg][0] = ex2(m_[mg][0] - mn0);
        alpha[mg][1] = ex2(m_[mg][1] - mn1);
        m_[mg][0] = mn0; m_[mg][1] = mn1;

        float sum0 = 0.0f, sum1 = 0.0f;
#pragma unroll
        for (int nf = 0; nf < 4; nf++) {
          s[mg][nf][0] = ex2(s[mg][nf][0] - mn0); sum0 += s[mg][nf][0];
          s[mg][nf][1] = ex2(s[mg][nf][1] - mn0); sum0 += s[mg][nf][1];
          s[mg][nf][2] = ex2(s[mg][nf][2] - mn1); sum1 += s[mg][nf][2];
          s[mg][nf][3] = ex2(s[mg][nf][3] - mn1); sum1 += s[mg][nf][3];
        }
#pragma unroll
        for (int off = 1; off <= 2; off <<= 1) {
          sum0 += __shfl_xor_sync(0xffffffffu, sum0, off);
          sum1 += __shfl_xor_sync(0xffffffffu, sum1, off);
        }
        l_[mg][0] = l_[mg][0] * alpha[mg][0] + sum0;
        l_[mg][1] = l_[mg][1] * alpha[mg][1] + sum1;
      }

      if (__any_sync(0xffffffffu,
                     (alpha[0][0] != 1.0f) | (alpha[0][1] != 1.0f) |
                     (alpha[1][0] != 1.0f) | (alpha[1][1] != 1.0f))) {
#pragma unroll
        for (int mg = 0; mg < 2; mg++)
#pragma unroll
          for (int dg = 0; dg < 16; dg++) {
            o[mg][dg][0] *= alpha[mg][0]; o[mg][dg][1] *= alpha[mg][0];
            o[mg][dg][2] *= alpha[mg][1]; o[mg][dg][3] *= alpha[mg][1];
          }
      }

      // ---- PV ----
#pragma unroll
      for (int cc = 0; cc < 2; cc++) {
        u32 ph[2][4], pl[2][4];
#pragma unroll
        for (int mg = 0; mg < 2; mg++) {
          float e[8] = { s[mg][2*cc][0],   s[mg][2*cc][1],   s[mg][2*cc][2],   s[mg][2*cc][3],
                         s[mg][2*cc+1][0], s[mg][2*cc+1][1], s[mg][2*cc+1][2], s[mg][2*cc+1][3] };
          const int map[4][2] = {{0,1},{2,3},{4,5},{6,7}};
#pragma unroll
          for (int q = 0; q < 4; q++) {
            float x0 = e[map[q][0]], x1 = e[map[q][1]];
            u32 hp = cvt2(x1, x0);
            float h0 = __uint_as_float(hp << 16);
            float h1 = __uint_as_float(hp & 0xffff0000u);
            ph[mg][q] = hp;
            pl[mg][q] = cvt2(x1 - h1, x0 - h0);
          }
        }
        const int oV = bb + BVH + g * VSTR + t * 4 + kh * 64 + cc * 32;
#pragma unroll
        for (int dg = 0; dg < 16; dg++) {
          const int vb = oV + dg * 8 * VSTR;
          u32 vh0 = *(const u32*)(smem + vb);
          u32 vh1 = *(const u32*)(smem + vb + 16);
          u32 vl0 = *(const u32*)(smem + vb + 18432);
          u32 vl1 = *(const u32*)(smem + vb + 18432 + 16);
#pragma unroll
          for (int mg = 0; mg < 2; mg++) {
            mma16816(o[mg][dg], ph[mg][0], ph[mg][1], ph[mg][2], ph[mg][3], vh0, vh1);
            mma16816(o[mg][dg], pl[mg][0], pl[mg][1], pl[mg][2], pl[mg][3], vh0, vh1);
            mma16816(o[mg][dg], ph[mg][0], ph[mg][1], ph[mg][2], ph[mg][3], vl0, vl1);
          }
        }
      }

      __syncthreads();
      if (it < 6) {
        issue_K(t0 + it + 2, it & 1);
        issue_V(t0 + it + 2, it & 1);
        CP_COMMIT();
      }
    }

    // ---- unit epilogue: merge kh halves, write partial to g_*16[ch] ----
    __syncthreads();
    float* Ob = (float*)(smem + SBUF);
    float* marr = (float*)(smem + SRED);
    float* larr = marr + 128;
    if (kh == 0) {
#pragma unroll
      for (int mg = 0; mg < 2; mg++) {
        int r0 = 32 * rg + 16 * mg + g;
#pragma unroll
        for (int dg = 0; dg < 16; dg++) {
          int c0 = 8 * dg + 2 * t;
          Ob[r0 * 128 + c0]           = o[mg][dg][0];
          Ob[r0 * 128 + c0 + 1]       = o[mg][dg][1];
          Ob[(r0 + 8) * 128 + c0]     = o[mg][dg][2];
          Ob[(r0 + 8) * 128 + c0 + 1] = o[mg][dg][3];
        }
        if (t == 0) {
          marr[r0] = m_[mg][0];     larr[r0] = l_[mg][0];
          marr[r0 + 8] = m_[mg][1]; larr[r0 + 8] = l_[mg][1];
        }
      }
    }
    __syncthreads();
    if (kh == 1) {
      float* gop = &g_Op16[ch][(size_t)(qb * 128) * D_HEAD];
#pragma unroll
      for (int mg = 0; mg < 2; mg++) {
        int r0 = 32 * rg + 16 * mg + g;
#pragma unroll
        for (int hh = 0; hh < 2; hh++) {
          int r = r0 + 8 * hh;
          float pm = marr[r], pL = larr[r];
          float M = fmaxf(m_[mg][hh], pm);
          float ws = ex2(m_[mg][hh] - M), wo = ex2(pm - M);
          float lm = ws * l_[mg][hh] + wo * pL;
          if (t == 0) {
            g_m16[ch][qb * 128 + r] = M;
            g_l16[ch][qb * 128 + r] = lm;
          }
#pragma unroll
          for (int dg = 0; dg < 16; dg++) {
            int c0 = 8 * dg + 2 * t;
            float v0 = ws * o[mg][dg][2 * hh]     + wo * Ob[r * 128 + c0];
            float v1 = ws * o[mg][dg][2 * hh + 1] + wo * Ob[r * 128 + c0 + 1];
            *(float2*)&gop[(size_t)r * D_HEAD + c0] = make_float2(v0, v1);
          }
        }
      }
    }
    __syncthreads();   // Ob (aliases K/V buffers) fully consumed before next unit
  }
}

// ---------------------------------------------------------------------------
// 16-way split-K combine (log2 domain m).
// ---------------------------------------------------------------------------
__global__ __launch_bounds__(256) void combine_kernel(float* __restrict__ out) {
  int idx = blockIdx.x * 256 + threadIdx.x;
  int r = idx >> 7;
  float M = -1e30f;
#pragma unroll
  for (int ch = 0; ch < 16; ch++) M = fmaxf(M, g_m16[ch][r]);
  float denom = 0.0f, acc = 0.0f;
#pragma unroll
  for (int ch = 0; ch < 16; ch++) {
    float wgt = ex2(g_m16[ch][r] - M);
    denom += wgt * g_l16[ch][r];
    acc   += wgt * g_Op16[ch][idx];
  }
  out[idx] = acc / denom;
}

// ---------------------------------------------------------------------------
extern "C" void kernel_launch(void* const* d_in, const int* in_sizes, int n_in,
                              void* d_out, int out_size) {
  const float* x  = (const float*)d_in[0];
  const float* Wq = (const float*)d_in[1];
  const float* Wk = (const float*)d_in[2];
  const float* Wv = (const float*)d_in[3];
  float* out = (float*)d_out;

  cudaFuncSetAttribute(attn_kernel,
                       cudaFuncAttributeMaxDynamicSharedMemorySize, ATT_SMEM);
  cudaFuncSetAttribute(proj_mma_kernel,
                       cudaFuncAttributeMaxDynamicSharedMemorySize, PROJ_SMEM);

  int nsm = 148;
  cudaDeviceGetAttribute(&nsm, cudaDevAttrMultiProcessorCount, 0);
  if (nsm < 1) nsm = 148;
  if (nsm > 1024) nsm = 1024;

  split_x_kernel<<<(N_TOK * D_IN) / 2048, 256>>>(x);
  split_w_kernel<<<dim3((D_HEAD * D_IN) / 2048, 3), 256>>>(Wq, Wk, Wv);
  proj_mma_kernel<<<dim3(N_TOK / 64, 3), 256, PROJ_SMEM>>>();
  attn_kernel<<<nsm, 256, ATT_SMEM>>>();
  combine_kernel<<<(N_TOK * D_HEAD) / 256, 256>>>(out);
}